// round 2
// baseline (speedup 1.0000x reference)
#include <cuda_runtime.h>
#include <math.h>
#include <stdint.h>

// ---------------- problem constants ----------------
#define BATCH  32
#define HEADS  12
#define SEQ    512
#define LHALF  256
#define DMODEL 768
#define HH     384          // hidden per direction
#define G4     1536         // 4*HH gates
#define DIN    1536         // 2*DMODEL LSTM input
#define BH     384          // BATCH*HEADS
#define TT     6            // SLIDER
#define EPSV   1e-9f

// ---------------- device scratch (no allocs allowed) ----------------
__device__ int   g_master[BH * 2];                     // [bh][half]
__device__ float g_slide[(size_t)BH * TT * DIN];       // 2304 x 1536
__device__ float g_gatesX[(size_t)BH * TT * 2 * G4];   // 2304 x 3072 (fwd | rev)
__device__ float g_gtmp[(size_t)2 * BH * G4];          // per-step h @ whh^T
__device__ float g_h[(size_t)2 * BH * HH];
__device__ float g_c[(size_t)2 * BH * HH];
__device__ float g_compose[(size_t)BH * TT * DMODEL];  // [n][t][fwd|bwd]
__device__ float g_lrep[(size_t)BATCH * DMODEL];

// ---------------- helpers ----------------
__device__ __forceinline__ float sigf(float x) { return 1.0f / (1.0f + expf(-x)); }

__device__ __forceinline__ int window_start(int pos) {
    pos = min(max(pos, 1), LHALF - 2);
    int l = TT / 2;                          // 3
    if (pos - TT / 2 <= 0) l = pos - 1;
    int r = TT - l;
    if (pos + r >= LHALF - 1) l = TT - (LHALF - pos - 2);
    return pos - l;
}

// ---------------- K1: masters (row-sum + argmax over 256x256 quadrant) ----------------
__global__ void masters_kernel(const float* __restrict__ att, const int* __restrict__ sents) {
    int bid  = blockIdx.x;           // [0, BH*2)
    int half = bid & 1;
    int bh   = bid >> 1;
    int b    = bh / HEADS;

    __shared__ unsigned char seps[LHALF];
    __shared__ float rowsum[LHALF];

    int tid = threadIdx.x;           // 256 threads
    // sep flags on key axis (applies to this half's key range)
    {
        int j = half * LHALF + tid;
        seps[tid] = (sents[b * SEQ + j] == 102) ? 1 : 0;
    }
    __syncthreads();

    const float* base = att + ((size_t)bh * SEQ + (size_t)half * LHALF) * SEQ + (size_t)half * LHALF;

    int warp = tid >> 5, lane = tid & 31;
    for (int row = warp; row < LHALF; row += 8) {
        const float* rp = base + (size_t)row * SEQ;
        float s = 0.0f;
        #pragma unroll
        for (int k = 0; k < 8; k++) {
            int j = lane + 32 * k;
            float v = rp[j];
            s += seps[j] ? EPSV : v;
        }
        #pragma unroll
        for (int off = 16; off > 0; off >>= 1)
            s += __shfl_down_sync(0xffffffffu, s, off);
        if (lane == 0) rowsum[row] = s;
    }
    __syncthreads();

    // argmax, first index wins ties
    __shared__ float bv[LHALF];
    __shared__ int   bix[LHALF];
    bv[tid]  = rowsum[tid];
    bix[tid] = tid;
    __syncthreads();
    for (int off = 128; off > 0; off >>= 1) {
        if (tid < off) {
            float vo = bv[tid + off];
            int   io = bix[tid + off];
            if (vo > bv[tid] || (vo == bv[tid] && io < bix[tid])) { bv[tid] = vo; bix[tid] = io; }
        }
        __syncthreads();
    }
    if (tid == 0) g_master[bh * 2 + half] = bix[0];
}

// ---------------- K2: gather windows -> slide ----------------
__global__ void build_slide(const float* __restrict__ logits, const int* __restrict__ mask) {
    int bh = blockIdx.x;             // [0, BH)
    int b  = bh / HEADS;
    __shared__ int sa, sb;
    if (threadIdx.x == 0) {
        sa = window_start(g_master[bh * 2 + 0]);
        sb = window_start(g_master[bh * 2 + 1]);
    }
    __syncthreads();

    for (int idx = threadIdx.x; idx < TT * DIN; idx += blockDim.x) {
        int t = idx / DIN, f = idx % DIN;
        float v;
        if (f < DMODEL) {
            int row = sa + t;
            v = (mask[b * SEQ + row] == 0) ? EPSV
                : logits[((size_t)b * SEQ + row) * DMODEL + f];
        } else {
            int row = LHALF + sb + t;
            v = (mask[b * SEQ + row] == 0) ? EPSV
                : logits[((size_t)b * SEQ + row) * DMODEL + (f - DMODEL)];
        }
        g_slide[(size_t)bh * (TT * DIN) + idx] = v;
    }
}

// ---------------- K3: zero h/c state ----------------
__global__ void zero_hc() {
    int i = blockIdx.x * blockDim.x + threadIdx.x;
    if (i < 2 * BH * HH) { g_h[i] = 0.0f; g_c[i] = 0.0f; }
}

// ---------------- K4: input GEMM  C[2304,3072] = slide @ [Wf;Wr]^T + biases ----------------
__global__ void input_gemm(const float* __restrict__ Wf, const float* __restrict__ Wr,
                           const float* __restrict__ bihf, const float* __restrict__ bhhf,
                           const float* __restrict__ bihr, const float* __restrict__ bhhr) {
    const int K = DIN;
    __shared__ float As[16][65];
    __shared__ float Bs[16][65];

    int bm = blockIdx.y * 64;
    int bn = blockIdx.x * 64;            // global n in [0, 3072)
    bool rev = (bn >= G4);
    const float* W = rev ? Wr : Wf;
    int bnl = rev ? (bn - G4) : bn;

    int tid = threadIdx.x;               // 256 threads
    int tx = tid & 15, ty = tid >> 4;
    float acc[4][4] = {};

    for (int k0 = 0; k0 < K; k0 += 16) {
        #pragma unroll
        for (int i = 0; i < 4; i++) {
            int e = tid + i * 256;
            int r = e >> 4, c = e & 15;
            As[c][r] = g_slide[(size_t)(bm + r) * K + k0 + c];
            Bs[c][r] = W[(size_t)(bnl + r) * K + k0 + c];
        }
        __syncthreads();
        #pragma unroll
        for (int kk = 0; kk < 16; kk++) {
            float a[4], bb[4];
            #pragma unroll
            for (int i = 0; i < 4; i++) a[i] = As[kk][ty * 4 + i];
            #pragma unroll
            for (int j = 0; j < 4; j++) bb[j] = Bs[kk][tx * 4 + j];
            #pragma unroll
            for (int i = 0; i < 4; i++)
                #pragma unroll
                for (int j = 0; j < 4; j++)
                    acc[i][j] += a[i] * bb[j];
        }
        __syncthreads();
    }

    #pragma unroll
    for (int i = 0; i < 4; i++) {
        int m = bm + ty * 4 + i;
        #pragma unroll
        for (int j = 0; j < 4; j++) {
            int nl = bnl + tx * 4 + j;
            float bias = rev ? (bihr[nl] + bhhr[nl]) : (bihf[nl] + bhhf[nl]);
            g_gatesX[(size_t)m * (2 * G4) + bn + tx * 4 + j] = acc[i][j] + bias;
        }
    }
}

// ---------------- K5: per-step recurrent GEMM  gtmp[dir] = h[dir] @ whh[dir]^T ----------------
__global__ void hgemm(const float* __restrict__ whhf, const float* __restrict__ whhr) {
    const int K = HH;
    int dir = blockIdx.z;
    const float* A = g_h + (size_t)dir * BH * HH;       // 384 x 384
    const float* W = dir ? whhr : whhf;                  // 1536 x 384
    float* C = g_gtmp + (size_t)dir * BH * G4;           // 384 x 1536

    __shared__ float As[16][65];
    __shared__ float Bs[16][65];

    int bm = blockIdx.y * 64;
    int bn = blockIdx.x * 64;
    int tid = threadIdx.x;
    int tx = tid & 15, ty = tid >> 4;
    float acc[4][4] = {};

    for (int k0 = 0; k0 < K; k0 += 16) {
        #pragma unroll
        for (int i = 0; i < 4; i++) {
            int e = tid + i * 256;
            int r = e >> 4, c = e & 15;
            As[c][r] = A[(size_t)(bm + r) * K + k0 + c];
            Bs[c][r] = W[(size_t)(bn + r) * K + k0 + c];
        }
        __syncthreads();
        #pragma unroll
        for (int kk = 0; kk < 16; kk++) {
            float a[4], bb[4];
            #pragma unroll
            for (int i = 0; i < 4; i++) a[i] = As[kk][ty * 4 + i];
            #pragma unroll
            for (int j = 0; j < 4; j++) bb[j] = Bs[kk][tx * 4 + j];
            #pragma unroll
            for (int i = 0; i < 4; i++)
                #pragma unroll
                for (int j = 0; j < 4; j++)
                    acc[i][j] += a[i] * bb[j];
        }
        __syncthreads();
    }

    #pragma unroll
    for (int i = 0; i < 4; i++)
        #pragma unroll
        for (int j = 0; j < 4; j++)
            C[(size_t)(bm + ty * 4 + i) * G4 + bn + tx * 4 + j] = acc[i][j];
}

// ---------------- K6: per-step LSTM pointwise (both directions) ----------------
__global__ void lstm_point(int s) {
    int idx = blockIdx.x * blockDim.x + threadIdx.x;    // 2*384*384
    if (idx >= 2 * BH * HH) return;
    int dir = idx / (BH * HH);
    int r   = idx % (BH * HH);
    int n   = r / HH;
    int j   = r % HH;
    int t   = dir ? (TT - 1 - s) : s;                   // reverse scan alignment

    const float* G0 = g_gatesX + ((size_t)(n * TT + t)) * (2 * G4) + (size_t)dir * G4;
    const float* T0 = g_gtmp + (size_t)dir * BH * G4 + (size_t)n * G4;

    float gi = G0[j]            + T0[j];
    float gf = G0[HH + j]       + T0[HH + j];
    float gg = G0[2 * HH + j]   + T0[2 * HH + j];
    float go = G0[3 * HH + j]   + T0[3 * HH + j];

    size_t st = (size_t)dir * BH * HH + (size_t)n * HH + j;
    float c = sigf(gf) * g_c[st] + sigf(gi) * tanhf(gg);
    float h = sigf(go) * tanhf(c);
    g_c[st] = c;
    g_h[st] = h;
    g_compose[((size_t)n * TT + t) * DMODEL + dir * HH + j] = h;
}

// ---------------- K7: logits_rep (mean of logits with window/mask replacement) ----------------
__global__ void logits_rep_kernel(const float* __restrict__ logits, const int* __restrict__ mask) {
    int b = blockIdx.x;
    int tid = threadIdx.x;                              // 256

    __shared__ unsigned char repl[SEQ];
    for (int i = tid; i < SEQ; i += blockDim.x) repl[i] = 0;
    __syncthreads();
    if (tid < 2 * HEADS) {
        int h = tid >> 1, half = tid & 1;
        int st = window_start(g_master[(b * HEADS + h) * 2 + half]);
        int base = half * LHALF + st;
        for (int k = 0; k < TT; k++) repl[base + k] = 1;   // benign same-value races
    }
    __syncthreads();
    for (int sPos = tid; sPos < SEQ; sPos += blockDim.x)
        repl[sPos] = (repl[sPos] && mask[b * SEQ + sPos] == 0) ? 1 : 0;
    __syncthreads();

    for (int d = tid; d < DMODEL; d += blockDim.x) {
        float acc = 0.0f;
        for (int sPos = 0; sPos < SEQ; sPos++) {
            float v = logits[((size_t)b * SEQ + sPos) * DMODEL + d];
            acc += repl[sPos] ? EPSV : v;
        }
        g_lrep[(size_t)b * DMODEL + d] = acc * (1.0f / (float)SEQ);
    }
}

// ---------------- K8: final FC (2 outputs) + softmax ----------------
__global__ void final_kernel(const float* __restrict__ fcw, const float* __restrict__ fcb,
                             float* __restrict__ out) {
    int b = blockIdx.x;
    int tid = threadIdx.x;                              // 256
    const int NF = DMODEL * (HEADS + 1);                // 9984
    float a0 = 0.0f, a1 = 0.0f;

    for (int j = tid; j < NF; j += 256) {
        float x;
        if (j < HEADS * DMODEL) {
            int h = j / DMODEL, d = j % DMODEL;
            int n = b * HEADS + h;
            const float* cp = g_compose + (size_t)n * TT * DMODEL + d;
            float s = 0.0f;
            #pragma unroll
            for (int t = 0; t < TT; t++) s += cp[(size_t)t * DMODEL];
            x = s * (1.0f / (float)TT);
        } else {
            x = g_lrep[(size_t)b * DMODEL + (j - HEADS * DMODEL)];
        }
        a0 += x * fcw[j];
        a1 += x * fcw[NF + j];
    }

    __shared__ float s0[256], s1[256];
    s0[tid] = a0; s1[tid] = a1;
    __syncthreads();
    for (int off = 128; off > 0; off >>= 1) {
        if (tid < off) { s0[tid] += s0[tid + off]; s1[tid] += s1[tid + off]; }
        __syncthreads();
    }
    if (tid == 0) {
        float l0 = s0[0] + fcb[0], l1 = s1[0] + fcb[1];
        float m = fmaxf(l0, l1);
        float e0 = expf(l0 - m), e1 = expf(l1 - m);
        float inv = 1.0f / (e0 + e1);
        out[b * 2 + 0] = e0 * inv;
        out[b * 2 + 1] = e1 * inv;
    }
}

// ---------------- launch ----------------
extern "C" void kernel_launch(void* const* d_in, const int* in_sizes, int n_in,
                              void* d_out, int out_size) {
    const int*   sents = (const int*)d_in[0];
    const float* att   = (const float*)d_in[1];
    const float* logits= (const float*)d_in[2];
    const int*   mask  = (const int*)d_in[3];
    const float* wih_f = (const float*)d_in[4];
    const float* whh_f = (const float*)d_in[5];
    const float* bih_f = (const float*)d_in[6];
    const float* bhh_f = (const float*)d_in[7];
    const float* wih_r = (const float*)d_in[8];
    const float* whh_r = (const float*)d_in[9];
    const float* bih_r = (const float*)d_in[10];
    const float* bhh_r = (const float*)d_in[11];
    const float* fc_w  = (const float*)d_in[12];
    const float* fc_b  = (const float*)d_in[13];
    float* out = (float*)d_out;

    masters_kernel<<<BH * 2, 256>>>(att, sents);
    build_slide<<<BH, 256>>>(logits, mask);
    zero_hc<<<(2 * BH * HH + 255) / 256, 256>>>();
    input_gemm<<<dim3(48, 36), 256>>>(wih_f, wih_r, bih_f, bhh_f, bih_r, bhh_r);
    for (int s = 0; s < TT; s++) {
        hgemm<<<dim3(G4 / 64, BH / 64, 2), 256>>>(whh_f, whh_r);
        lstm_point<<<(2 * BH * HH + 255) / 256, 256>>>(s);
    }
    logits_rep_kernel<<<BATCH, 256>>>(logits, mask);
    final_kernel<<<BATCH, 256>>>(fc_w, fc_b, out);
}

// round 3
// speedup vs baseline: 1.0033x; 1.0033x over previous
#include <cuda_runtime.h>
#include <math.h>
#include <stdint.h>

// ---------------- problem constants ----------------
#define BATCH  32
#define HEADS  12
#define SEQ    512
#define LHALF  256
#define DMODEL 768
#define HH     384          // hidden per direction
#define G4     1536         // 4*HH gates
#define DIN    1536         // 2*DMODEL LSTM input
#define BH     384          // BATCH*HEADS
#define TT     6            // SLIDER
#define EPSV   1e-9f

// ---------------- device scratch (no allocs allowed) ----------------
__device__ int   g_master[BH * 2];                     // [bh][half]
__device__ float g_slide[(size_t)BH * TT * DIN];       // 2304 x 1536
__device__ float g_gatesX[(size_t)BH * TT * 2 * G4];   // 2304 x 3072 (fwd | rev)
__device__ float g_gtmp[(size_t)2 * BH * G4];          // per-step h @ whh^T
__device__ float g_h[(size_t)2 * BH * HH];
__device__ float g_c[(size_t)2 * BH * HH];
__device__ float g_compose[(size_t)BH * TT * DMODEL];  // [n][t][fwd|bwd]
__device__ float g_lrep[(size_t)BATCH * DMODEL];

// ---------------- helpers ----------------
__device__ __forceinline__ float sigf(float x) { return 1.0f / (1.0f + expf(-x)); }

__device__ __forceinline__ int window_start(int pos) {
    pos = min(max(pos, 1), LHALF - 2);
    int l = TT / 2;                          // 3
    if (pos - TT / 2 <= 0) l = pos - 1;
    int r = TT - l;
    if (pos + r >= LHALF - 1) l = TT - (LHALF - pos - 2);
    return pos - l;
}

// ---------------- K1: masters (row-sum + argmax over 256x256 quadrant) ----------------
__global__ void masters_kernel(const float* __restrict__ att, const int* __restrict__ sents) {
    int bid  = blockIdx.x;           // [0, BH*2)
    int half = bid & 1;
    int bh   = bid >> 1;
    int b    = bh / HEADS;

    __shared__ unsigned char seps[LHALF];
    __shared__ float rowsum[LHALF];

    int tid = threadIdx.x;           // 256 threads
    // sep flags on key axis (applies to this half's key range)
    {
        int j = half * LHALF + tid;
        seps[tid] = (sents[b * SEQ + j] == 102) ? 1 : 0;
    }
    __syncthreads();

    const float* base = att + ((size_t)bh * SEQ + (size_t)half * LHALF) * SEQ + (size_t)half * LHALF;

    int warp = tid >> 5, lane = tid & 31;
    for (int row = warp; row < LHALF; row += 8) {
        const float* rp = base + (size_t)row * SEQ;
        float s = 0.0f;
        #pragma unroll
        for (int k = 0; k < 8; k++) {
            int j = lane + 32 * k;
            float v = rp[j];
            s += seps[j] ? EPSV : v;
        }
        #pragma unroll
        for (int off = 16; off > 0; off >>= 1)
            s += __shfl_down_sync(0xffffffffu, s, off);
        if (lane == 0) rowsum[row] = s;
    }
    __syncthreads();

    // argmax, first index wins ties
    __shared__ float bv[LHALF];
    __shared__ int   bix[LHALF];
    bv[tid]  = rowsum[tid];
    bix[tid] = tid;
    __syncthreads();
    for (int off = 128; off > 0; off >>= 1) {
        if (tid < off) {
            float vo = bv[tid + off];
            int   io = bix[tid + off];
            if (vo > bv[tid] || (vo == bv[tid] && io < bix[tid])) { bv[tid] = vo; bix[tid] = io; }
        }
        __syncthreads();
    }
    if (tid == 0) g_master[bh * 2 + half] = bix[0];
}

// ---------------- K2: gather windows -> slide ----------------
__global__ void build_slide(const float* __restrict__ logits, const int* __restrict__ mask) {
    int bh = blockIdx.x;             // [0, BH)
    int b  = bh / HEADS;
    __shared__ int sa, sb;
    if (threadIdx.x == 0) {
        sa = window_start(g_master[bh * 2 + 0]);
        sb = window_start(g_master[bh * 2 + 1]);
    }
    __syncthreads();

    for (int idx = threadIdx.x; idx < TT * DIN; idx += blockDim.x) {
        int t = idx / DIN, f = idx % DIN;
        float v;
        if (f < DMODEL) {
            int row = sa + t;
            v = (mask[b * SEQ + row] == 0) ? EPSV
                : logits[((size_t)b * SEQ + row) * DMODEL + f];
        } else {
            int row = LHALF + sb + t;
            v = (mask[b * SEQ + row] == 0) ? EPSV
                : logits[((size_t)b * SEQ + row) * DMODEL + (f - DMODEL)];
        }
        g_slide[(size_t)bh * (TT * DIN) + idx] = v;
    }
}

// ---------------- K3: zero h/c state ----------------
__global__ void zero_hc() {
    int i = blockIdx.x * blockDim.x + threadIdx.x;
    if (i < 2 * BH * HH) { g_h[i] = 0.0f; g_c[i] = 0.0f; }
}

// ---------------- K4: input GEMM  C[2304,3072] = slide @ [Wf;Wr]^T + biases ----------------
__global__ void input_gemm(const float* __restrict__ Wf, const float* __restrict__ Wr,
                           const float* __restrict__ bihf, const float* __restrict__ bhhf,
                           const float* __restrict__ bihr, const float* __restrict__ bhhr) {
    const int K = DIN;
    __shared__ float As[16][65];
    __shared__ float Bs[16][65];

    int bm = blockIdx.y * 64;
    int bn = blockIdx.x * 64;            // global n in [0, 3072)
    bool rev = (bn >= G4);
    const float* W = rev ? Wr : Wf;
    int bnl = rev ? (bn - G4) : bn;

    int tid = threadIdx.x;               // 256 threads
    int tx = tid & 15, ty = tid >> 4;
    float acc[4][4] = {};

    for (int k0 = 0; k0 < K; k0 += 16) {
        #pragma unroll
        for (int i = 0; i < 4; i++) {
            int e = tid + i * 256;
            int r = e >> 4, c = e & 15;
            As[c][r] = g_slide[(size_t)(bm + r) * K + k0 + c];
            Bs[c][r] = W[(size_t)(bnl + r) * K + k0 + c];
        }
        __syncthreads();
        #pragma unroll
        for (int kk = 0; kk < 16; kk++) {
            float a[4], bb[4];
            #pragma unroll
            for (int i = 0; i < 4; i++) a[i] = As[kk][ty * 4 + i];
            #pragma unroll
            for (int j = 0; j < 4; j++) bb[j] = Bs[kk][tx * 4 + j];
            #pragma unroll
            for (int i = 0; i < 4; i++)
                #pragma unroll
                for (int j = 0; j < 4; j++)
                    acc[i][j] += a[i] * bb[j];
        }
        __syncthreads();
    }

    #pragma unroll
    for (int i = 0; i < 4; i++) {
        int m = bm + ty * 4 + i;
        #pragma unroll
        for (int j = 0; j < 4; j++) {
            int nl = bnl + tx * 4 + j;
            float bias = rev ? (bihr[nl] + bhhr[nl]) : (bihf[nl] + bhhf[nl]);
            g_gatesX[(size_t)m * (2 * G4) + bn + tx * 4 + j] = acc[i][j] + bias;
        }
    }
}

// ---------------- K5: per-step recurrent GEMM  gtmp[dir] = h[dir] @ whh[dir]^T ----------------
__global__ void hgemm(const float* __restrict__ whhf, const float* __restrict__ whhr) {
    const int K = HH;
    int dir = blockIdx.z;
    const float* A = g_h + (size_t)dir * BH * HH;       // 384 x 384
    const float* W = dir ? whhr : whhf;                  // 1536 x 384
    float* C = g_gtmp + (size_t)dir * BH * G4;           // 384 x 1536

    __shared__ float As[16][65];
    __shared__ float Bs[16][65];

    int bm = blockIdx.y * 64;
    int bn = blockIdx.x * 64;
    int tid = threadIdx.x;
    int tx = tid & 15, ty = tid >> 4;
    float acc[4][4] = {};

    for (int k0 = 0; k0 < K; k0 += 16) {
        #pragma unroll
        for (int i = 0; i < 4; i++) {
            int e = tid + i * 256;
            int r = e >> 4, c = e & 15;
            As[c][r] = A[(size_t)(bm + r) * K + k0 + c];
            Bs[c][r] = W[(size_t)(bn + r) * K + k0 + c];
        }
        __syncthreads();
        #pragma unroll
        for (int kk = 0; kk < 16; kk++) {
            float a[4], bb[4];
            #pragma unroll
            for (int i = 0; i < 4; i++) a[i] = As[kk][ty * 4 + i];
            #pragma unroll
            for (int j = 0; j < 4; j++) bb[j] = Bs[kk][tx * 4 + j];
            #pragma unroll
            for (int i = 0; i < 4; i++)
                #pragma unroll
                for (int j = 0; j < 4; j++)
                    acc[i][j] += a[i] * bb[j];
        }
        __syncthreads();
    }

    #pragma unroll
    for (int i = 0; i < 4; i++)
        #pragma unroll
        for (int j = 0; j < 4; j++)
            C[(size_t)(bm + ty * 4 + i) * G4 + bn + tx * 4 + j] = acc[i][j];
}

// ---------------- K6: per-step LSTM pointwise (both directions) ----------------
__global__ void lstm_point(int s) {
    int idx = blockIdx.x * blockDim.x + threadIdx.x;    // 2*384*384
    if (idx >= 2 * BH * HH) return;
    int dir = idx / (BH * HH);
    int r   = idx % (BH * HH);
    int n   = r / HH;
    int j   = r % HH;
    int t   = dir ? (TT - 1 - s) : s;                   // reverse scan alignment

    const float* G0 = g_gatesX + ((size_t)(n * TT + t)) * (2 * G4) + (size_t)dir * G4;
    const float* T0 = g_gtmp + (size_t)dir * BH * G4 + (size_t)n * G4;

    float gi = G0[j]            + T0[j];
    float gf = G0[HH + j]       + T0[HH + j];
    float gg = G0[2 * HH + j]   + T0[2 * HH + j];
    float go = G0[3 * HH + j]   + T0[3 * HH + j];

    size_t st = (size_t)dir * BH * HH + (size_t)n * HH + j;
    float c = sigf(gf) * g_c[st] + sigf(gi) * tanhf(gg);
    float h = sigf(go) * tanhf(c);
    g_c[st] = c;
    g_h[st] = h;
    g_compose[((size_t)n * TT + t) * DMODEL + dir * HH + j] = h;
}

// ---------------- K7: logits_rep (mean of logits with window/mask replacement) ----------------
__global__ void logits_rep_kernel(const float* __restrict__ logits, const int* __restrict__ mask) {
    int b = blockIdx.x;
    int tid = threadIdx.x;                              // 256

    __shared__ unsigned char repl[SEQ];
    for (int i = tid; i < SEQ; i += blockDim.x) repl[i] = 0;
    __syncthreads();
    if (tid < 2 * HEADS) {
        int h = tid >> 1, half = tid & 1;
        int st = window_start(g_master[(b * HEADS + h) * 2 + half]);
        int base = half * LHALF + st;
        for (int k = 0; k < TT; k++) repl[base + k] = 1;   // benign same-value races
    }
    __syncthreads();
    for (int sPos = tid; sPos < SEQ; sPos += blockDim.x)
        repl[sPos] = (repl[sPos] && mask[b * SEQ + sPos] == 0) ? 1 : 0;
    __syncthreads();

    for (int d = tid; d < DMODEL; d += blockDim.x) {
        float acc = 0.0f;
        for (int sPos = 0; sPos < SEQ; sPos++) {
            float v = logits[((size_t)b * SEQ + sPos) * DMODEL + d];
            acc += repl[sPos] ? EPSV : v;
        }
        g_lrep[(size_t)b * DMODEL + d] = acc * (1.0f / (float)SEQ);
    }
}

// ---------------- K8: final FC (2 outputs) + softmax ----------------
__global__ void final_kernel(const float* __restrict__ fcw, const float* __restrict__ fcb,
                             float* __restrict__ out) {
    int b = blockIdx.x;
    int tid = threadIdx.x;                              // 256
    const int NF = DMODEL * (HEADS + 1);                // 9984
    float a0 = 0.0f, a1 = 0.0f;

    for (int j = tid; j < NF; j += 256) {
        float x;
        if (j < HEADS * DMODEL) {
            int h = j / DMODEL, d = j % DMODEL;
            int n = b * HEADS + h;
            const float* cp = g_compose + (size_t)n * TT * DMODEL + d;
            float s = 0.0f;
            #pragma unroll
            for (int t = 0; t < TT; t++) s += cp[(size_t)t * DMODEL];
            x = s * (1.0f / (float)TT);
        } else {
            x = g_lrep[(size_t)b * DMODEL + (j - HEADS * DMODEL)];
        }
        a0 += x * fcw[j];
        a1 += x * fcw[NF + j];
    }

    __shared__ float s0[256], s1[256];
    s0[tid] = a0; s1[tid] = a1;
    __syncthreads();
    for (int off = 128; off > 0; off >>= 1) {
        if (tid < off) { s0[tid] += s0[tid + off]; s1[tid] += s1[tid + off]; }
        __syncthreads();
    }
    if (tid == 0) {
        float l0 = s0[0] + fcb[0], l1 = s1[0] + fcb[1];
        float m = fmaxf(l0, l1);
        float e0 = expf(l0 - m), e1 = expf(l1 - m);
        float inv = 1.0f / (e0 + e1);
        out[b * 2 + 0] = e0 * inv;
        out[b * 2 + 1] = e1 * inv;
    }
}

// ---------------- launch ----------------
extern "C" void kernel_launch(void* const* d_in, const int* in_sizes, int n_in,
                              void* d_out, int out_size) {
    const int*   sents = (const int*)d_in[0];
    const float* att   = (const float*)d_in[1];
    const float* logits= (const float*)d_in[2];
    const int*   mask  = (const int*)d_in[3];
    const float* wih_f = (const float*)d_in[4];
    const float* whh_f = (const float*)d_in[5];
    const float* bih_f = (const float*)d_in[6];
    const float* bhh_f = (const float*)d_in[7];
    const float* wih_r = (const float*)d_in[8];
    const float* whh_r = (const float*)d_in[9];
    const float* bih_r = (const float*)d_in[10];
    const float* bhh_r = (const float*)d_in[11];
    const float* fc_w  = (const float*)d_in[12];
    const float* fc_b  = (const float*)d_in[13];
    float* out = (float*)d_out;

    masters_kernel<<<BH * 2, 256>>>(att, sents);
    build_slide<<<BH, 256>>>(logits, mask);
    zero_hc<<<(2 * BH * HH + 255) / 256, 256>>>();
    input_gemm<<<dim3(48, 36), 256>>>(wih_f, wih_r, bih_f, bhh_f, bih_r, bhh_r);
    for (int s = 0; s < TT; s++) {
        hgemm<<<dim3(G4 / 64, BH / 64, 2), 256>>>(whh_f, whh_r);
        lstm_point<<<(2 * BH * HH + 255) / 256, 256>>>(s);
    }
    logits_rep_kernel<<<BATCH, 256>>>(logits, mask);
    final_kernel<<<BATCH, 256>>>(fc_w, fc_b, out);
}

// round 6
// speedup vs baseline: 2.9633x; 2.9535x over previous
#include <cuda_runtime.h>
#include <cuda_bf16.h>
#include <math.h>
#include <stdint.h>

// ---------------- problem constants ----------------
#define BATCH  32
#define HEADS  12
#define SEQ    512
#define LHALF  256
#define DMODEL 768
#define HH     384          // hidden per direction
#define G4     1536         // 4*HH gates
#define DIN    1536         // 2*DMODEL LSTM input
#define BH     384          // BATCH*HEADS
#define TT     6            // SLIDER
#define EPSV   1e-9f

// ---------------- device scratch (no allocs allowed) ----------------
__device__ int   g_master[BH * 2];
__device__ float g_gatesX[(size_t)BH * TT * 2 * G4];   // 2304 x 3072 (fwd | rev), bias folded
__device__ float g_gtmp[(size_t)2 * BH * G4];          // per-step h @ whh^T
__device__ float g_c[(size_t)2 * BH * HH];
__device__ float g_compose[(size_t)BH * TT * DMODEL];
__device__ float g_lrep[(size_t)BATCH * DMODEL];

// bf16 split operands
__device__ __nv_bfloat16 g_slide_h[(size_t)BH * TT * DIN];
__device__ __nv_bfloat16 g_slide_l[(size_t)BH * TT * DIN];
__device__ __nv_bfloat16 g_wih_h[(size_t)2 * G4 * DIN];   // [3072][1536]
__device__ __nv_bfloat16 g_wih_l[(size_t)2 * G4 * DIN];
__device__ __nv_bfloat16 g_whh_h[(size_t)2 * G4 * HH];    // [2][1536][384]
__device__ __nv_bfloat16 g_whh_l[(size_t)2 * G4 * HH];
__device__ __nv_bfloat16 g_hb_h[(size_t)2 * BH * HH];     // [2][384][384]
__device__ __nv_bfloat16 g_hb_l[(size_t)2 * BH * HH];
__device__ float g_bias[2 * G4];

// ---------------- PTX helpers (baseline PTX only: sm_80-class ops) ----------------
__device__ __forceinline__ uint32_t smem_u32(const void* p) {
    uint32_t a;
    asm("{ .reg .u64 t; cvta.to.shared.u64 t, %1; cvt.u32.u64 %0, t; }" : "=r"(a) : "l"(p));
    return a;
}

#define CP_ASYNC16(sm, gm) \
    asm volatile("cp.async.cg.shared.global [%0], [%1], 16;" :: "r"(sm), "l"(gm) : "memory")
#define CP_COMMIT() asm volatile("cp.async.commit_group;" ::: "memory")
#define CP_WAIT0()  asm volatile("cp.async.wait_group 0;" ::: "memory")

#define LDSM_X4(r0, r1, r2, r3, addr) \
    asm volatile("ldmatrix.sync.aligned.m8n8.x4.shared.b16 {%0,%1,%2,%3}, [%4];" \
        : "=r"(r0), "=r"(r1), "=r"(r2), "=r"(r3) : "r"(addr))

#define MMA_BF16(c0, c1, c2, c3, a0, a1, a2, a3, b0, b1) \
    asm volatile("mma.sync.aligned.m16n8k16.row.col.f32.bf16.bf16.f32 " \
        "{%0,%1,%2,%3}, {%4,%5,%6,%7}, {%8,%9}, {%0,%1,%2,%3};" \
        : "+f"(c0), "+f"(c1), "+f"(c2), "+f"(c3) \
        : "r"(a0), "r"(a1), "r"(a2), "r"(a3), "r"(b0), "r"(b1))

// ---------------- helpers ----------------
__device__ __forceinline__ float sigf(float x) { return 1.0f / (1.0f + expf(-x)); }

__device__ __forceinline__ int window_start(int pos) {
    pos = min(max(pos, 1), LHALF - 2);
    int l = TT / 2;
    if (pos - TT / 2 <= 0) l = pos - 1;
    int r = TT - l;
    if (pos + r >= LHALF - 1) l = TT - (LHALF - pos - 2);
    return pos - l;
}

// ---------------- K1: masters ----------------
__global__ void masters_kernel(const float* __restrict__ att, const int* __restrict__ sents) {
    int bid  = blockIdx.x;
    int half = bid & 1;
    int bh   = bid >> 1;
    int b    = bh / HEADS;

    __shared__ unsigned char seps[LHALF];
    __shared__ float rowsum[LHALF];

    int tid = threadIdx.x;
    {
        int j = half * LHALF + tid;
        seps[tid] = (sents[b * SEQ + j] == 102) ? 1 : 0;
    }
    __syncthreads();

    const float* base = att + ((size_t)bh * SEQ + (size_t)half * LHALF) * SEQ + (size_t)half * LHALF;

    int warp = tid >> 5, lane = tid & 31;
    for (int row = warp; row < LHALF; row += 8) {
        const float* rp = base + (size_t)row * SEQ;
        float s = 0.0f;
        #pragma unroll
        for (int k = 0; k < 8; k++) {
            int j = lane + 32 * k;
            float v = rp[j];
            s += seps[j] ? EPSV : v;
        }
        #pragma unroll
        for (int off = 16; off > 0; off >>= 1)
            s += __shfl_down_sync(0xffffffffu, s, off);
        if (lane == 0) rowsum[row] = s;
    }
    __syncthreads();

    __shared__ float bv[LHALF];
    __shared__ int   bix[LHALF];
    bv[tid]  = rowsum[tid];
    bix[tid] = tid;
    __syncthreads();
    for (int off = 128; off > 0; off >>= 1) {
        if (tid < off) {
            float vo = bv[tid + off];
            int   io = bix[tid + off];
            if (vo > bv[tid] || (vo == bv[tid] && io < bix[tid])) { bv[tid] = vo; bix[tid] = io; }
        }
        __syncthreads();
    }
    if (tid == 0) g_master[bh * 2 + half] = bix[0];
}

// ---------------- K2: gather windows -> slide (bf16 hi/lo) ----------------
__global__ void build_slide(const float* __restrict__ logits, const int* __restrict__ mask) {
    int bh = blockIdx.x;
    int b  = bh / HEADS;
    __shared__ int sa, sb;
    if (threadIdx.x == 0) {
        sa = window_start(g_master[bh * 2 + 0]);
        sb = window_start(g_master[bh * 2 + 1]);
    }
    __syncthreads();

    for (int idx = threadIdx.x; idx < TT * DIN; idx += blockDim.x) {
        int t = idx / DIN, f = idx % DIN;
        float v;
        if (f < DMODEL) {
            int row = sa + t;
            v = (mask[b * SEQ + row] == 0) ? EPSV
                : logits[((size_t)b * SEQ + row) * DMODEL + f];
        } else {
            int row = LHALF + sb + t;
            v = (mask[b * SEQ + row] == 0) ? EPSV
                : logits[((size_t)b * SEQ + row) * DMODEL + (f - DMODEL)];
        }
        size_t off = (size_t)bh * (TT * DIN) + idx;
        __nv_bfloat16 hi = __float2bfloat16(v);
        g_slide_h[off] = hi;
        g_slide_l[off] = __float2bfloat16(v - __bfloat162float(hi));
    }
}

// ---------------- K3: weight split + bias combine + state zero ----------------
__global__ void split_kernel(const float* __restrict__ src, int mode, size_t dstoff, int n) {
    int i = blockIdx.x * blockDim.x + threadIdx.x;
    if (i >= n) return;
    float x = src[i];
    __nv_bfloat16 hi = __float2bfloat16(x);
    __nv_bfloat16 lo = __float2bfloat16(x - __bfloat162float(hi));
    if (mode == 0) { g_wih_h[dstoff + i] = hi; g_wih_l[dstoff + i] = lo; }
    else           { g_whh_h[dstoff + i] = hi; g_whh_l[dstoff + i] = lo; }
}

__global__ void bias_combine(const float* __restrict__ bihf, const float* __restrict__ bhhf,
                             const float* __restrict__ bihr, const float* __restrict__ bhhr) {
    int i = blockIdx.x * blockDim.x + threadIdx.x;
    if (i >= 2 * G4) return;
    g_bias[i] = (i < G4) ? (bihf[i] + bhhf[i]) : (bihr[i - G4] + bhhr[i - G4]);
}

__global__ void zero_state() {
    int i = blockIdx.x * blockDim.x + threadIdx.x;
    __nv_bfloat16 z = __float2bfloat16(0.0f);
    if (i < 2 * BH * HH) { g_c[i] = 0.0f; g_hb_h[i] = z; g_hb_l[i] = z; }
    if (i < 2 * BH * G4) g_gtmp[i] = 0.0f;
}

// ---------------- K4: HMMA GEMM (mma.sync bf16 3-product split, fp32 accum) ----------------
// C[m][n] = sum_k A[m][k]*B[n][k] (+bias[n])
// mode 0: A=slide(2304x1536) B=wih(3072x1536) C=gatesX, bias
// mode 1: A=hb[z](384x384)   B=whh[z](1536x384) C=gtmp[z]
#define BK          64
#define CHUNK_BYTES 16384          // 128 rows x 128B (64 bf16)
#define BUF_BYTES   (4 * CHUNK_BYTES)
#define GM_SMEM     (1024 + 2 * BUF_BYTES)

__global__ __launch_bounds__(256, 1) void gemm_hmma(int mode) {
    extern __shared__ char smem_raw[];
    uint32_t smem_u = smem_u32(smem_raw);
    uint32_t tiles_u = (smem_u + 1023) & ~1023u;

    const __nv_bfloat16 *Ah, *Al, *Bh, *Bl;
    float* C;
    const float* bias;
    int K;
    int z = blockIdx.z;
    if (mode == 0) {
        Ah = g_slide_h; Al = g_slide_l; Bh = g_wih_h; Bl = g_wih_l;
        C = g_gatesX; bias = g_bias; K = DIN;
    } else {
        size_t za = (size_t)z * BH * HH, zb = (size_t)z * G4 * HH;
        Ah = g_hb_h + za; Al = g_hb_l + za; Bh = g_whh_h + zb; Bl = g_whh_l + zb;
        C = g_gtmp + (size_t)z * BH * G4; bias = nullptr; K = HH;
    }

    int tid = threadIdx.x;
    int wid = tid >> 5;
    int lane = tid & 31;

    int bm = blockIdx.y * 128;
    int bn = blockIdx.x * 128;
    int ldc = gridDim.x * 128;
    int NC = K / BK;
    int Kd8 = K >> 3;

    const __nv_bfloat16* srcs[4] = {Ah, Al, Bh, Bl};
    int rows0[4] = {bm, bm, bn, bn};

    // async-load one K-chunk (Ah|Al|Bh|Bl, each 128x64 bf16, SW128-xor swizzled)
    auto load_chunk = [&](int c, int buf) {
        int k0 = c * BK;
        uint32_t bufu = tiles_u + buf * BUF_BYTES;
        #pragma unroll
        for (int t4 = 0; t4 < 4; t4++) {
            const uint4* gp = (const uint4*)(srcs[t4] + (size_t)rows0[t4] * K + k0);
            uint32_t tb = bufu + t4 * CHUNK_BYTES;
            #pragma unroll
            for (int i = 0; i < 2; i++) {
                int u = tid + i * 256;          // 512 uint4 per 16KB... (1024 total, 4 per thread)
                int r0 = (u >> 3) * 2;          // process two rows per step below
                (void)r0;
            }
            #pragma unroll
            for (int i = 0; i < 4; i++) {
                int u = tid + i * 256;
                int r = u >> 3, c16 = u & 7;
                const uint4* ga = gp + (size_t)r * Kd8 + c16;
                uint32_t off = (uint32_t)(r * 128 + c16 * 16);
                uint32_t sw = off ^ ((off >> 3) & 0x70);
                CP_ASYNC16(tb + sw, ga);
            }
        }
    };

    // warp layout: 2(M) x 4(N); warp tile 64 x 32
    int wm = (wid & 1) * 64;
    int wn = (wid >> 1) * 32;

    float acc[4][4][4];
    #pragma unroll
    for (int i = 0; i < 4; i++)
        #pragma unroll
        for (int j = 0; j < 4; j++)
            #pragma unroll
            for (int q = 0; q < 4; q++) acc[i][j][q] = 0.0f;

    load_chunk(0, 0);
    CP_COMMIT();

    for (int c = 0; c < NC; c++) {
        CP_WAIT0();
        __syncthreads();
        if (c + 1 < NC) { load_chunk(c + 1, (c + 1) & 1); CP_COMMIT(); }

        uint32_t base = tiles_u + (c & 1) * BUF_BYTES;
        #pragma unroll
        for (int p = 0; p < 3; p++) {          // (Ah,Bh) (Ah,Bl) (Al,Bh)
            uint32_t abase = base + ((p == 2) ? CHUNK_BYTES : 0);
            uint32_t bbase = base + 2 * CHUNK_BYTES + ((p == 1) ? CHUNK_BYTES : 0);
            #pragma unroll
            for (int ks = 0; ks < 4; ks++) {
                // A fragments: 4 m16 tiles
                uint32_t a[4][4];
                #pragma unroll
                for (int mt = 0; mt < 4; mt++) {
                    uint32_t r = wm + mt * 16 + (lane & 15);
                    uint32_t coloff = ks * 32 + ((lane >> 4) & 1) * 16;
                    uint32_t off = r * 128 + coloff;
                    uint32_t addr = abase + (off ^ ((off >> 3) & 0x70));
                    LDSM_X4(a[mt][0], a[mt][1], a[mt][2], a[mt][3], addr);
                }
                // B fragments: 4 n8 tiles (two x4 ldmatrix)
                uint32_t b[4][2];
                #pragma unroll
                for (int h = 0; h < 2; h++) {
                    uint32_t r = wn + h * 16 + (lane & 7) + ((lane >> 4) << 3);
                    uint32_t coloff = ks * 32 + ((lane >> 3) & 1) * 16;
                    uint32_t off = r * 128 + coloff;
                    uint32_t addr = bbase + (off ^ ((off >> 3) & 0x70));
                    uint32_t r0, r1, r2, r3;
                    LDSM_X4(r0, r1, r2, r3, addr);
                    b[2 * h][0] = r0; b[2 * h][1] = r1;
                    b[2 * h + 1][0] = r2; b[2 * h + 1][1] = r3;
                }
                #pragma unroll
                for (int mt = 0; mt < 4; mt++)
                    #pragma unroll
                    for (int nt = 0; nt < 4; nt++)
                        MMA_BF16(acc[mt][nt][0], acc[mt][nt][1], acc[mt][nt][2], acc[mt][nt][3],
                                 a[mt][0], a[mt][1], a[mt][2], a[mt][3],
                                 b[nt][0], b[nt][1]);
            }
        }
        __syncthreads();
    }

    // epilogue
    #pragma unroll
    for (int mt = 0; mt < 4; mt++) {
        #pragma unroll
        for (int nt = 0; nt < 4; nt++) {
            int row = bm + wm + mt * 16 + (lane >> 2);
            int col = bn + wn + nt * 8 + (lane & 3) * 2;
            float b0 = 0.0f, b1 = 0.0f;
            if (bias) { b0 = bias[col]; b1 = bias[col + 1]; }
            float2 v0 = make_float2(acc[mt][nt][0] + b0, acc[mt][nt][1] + b1);
            float2 v1 = make_float2(acc[mt][nt][2] + b0, acc[mt][nt][3] + b1);
            *(float2*)(C + (size_t)row * ldc + col) = v0;
            *(float2*)(C + (size_t)(row + 8) * ldc + col) = v1;
        }
    }
}

// ---------------- K6: per-step LSTM pointwise (writes bf16 h split directly) ----------------
__global__ void lstm_point(int s) {
    int idx = blockIdx.x * blockDim.x + threadIdx.x;
    if (idx >= 2 * BH * HH) return;
    int dir = idx / (BH * HH);
    int r   = idx % (BH * HH);
    int n   = r / HH;
    int j   = r % HH;
    int t   = dir ? (TT - 1 - s) : s;

    const float* G0 = g_gatesX + ((size_t)(n * TT + t)) * (2 * G4) + (size_t)dir * G4;
    const float* T0 = g_gtmp + (size_t)dir * BH * G4 + (size_t)n * G4;

    float gi = G0[j]          + T0[j];
    float gf = G0[HH + j]     + T0[HH + j];
    float gg = G0[2 * HH + j] + T0[2 * HH + j];
    float go = G0[3 * HH + j] + T0[3 * HH + j];

    size_t st = (size_t)dir * BH * HH + (size_t)n * HH + j;
    float c = sigf(gf) * g_c[st] + sigf(gi) * tanhf(gg);
    float h = sigf(go) * tanhf(c);
    g_c[st] = c;
    __nv_bfloat16 hi = __float2bfloat16(h);
    g_hb_h[st] = hi;
    g_hb_l[st] = __float2bfloat16(h - __bfloat162float(hi));
    g_compose[((size_t)n * TT + t) * DMODEL + dir * HH + j] = h;
}

// ---------------- K7: logits_rep ----------------
__global__ void logits_rep_kernel(const float* __restrict__ logits, const int* __restrict__ mask) {
    int b = blockIdx.x;
    int tid = threadIdx.x;

    __shared__ unsigned char repl[SEQ];
    for (int i = tid; i < SEQ; i += blockDim.x) repl[i] = 0;
    __syncthreads();
    if (tid < 2 * HEADS) {
        int h = tid >> 1, half = tid & 1;
        int st = window_start(g_master[(b * HEADS + h) * 2 + half]);
        int base = half * LHALF + st;
        for (int k = 0; k < TT; k++) repl[base + k] = 1;
    }
    __syncthreads();
    for (int sPos = tid; sPos < SEQ; sPos += blockDim.x)
        repl[sPos] = (repl[sPos] && mask[b * SEQ + sPos] == 0) ? 1 : 0;
    __syncthreads();

    for (int d = tid; d < DMODEL; d += blockDim.x) {
        float acc = 0.0f;
        for (int sPos = 0; sPos < SEQ; sPos++) {
            float v = logits[((size_t)b * SEQ + sPos) * DMODEL + d];
            acc += repl[sPos] ? EPSV : v;
        }
        g_lrep[(size_t)b * DMODEL + d] = acc * (1.0f / (float)SEQ);
    }
}

// ---------------- K8: final FC + softmax ----------------
__global__ void final_kernel(const float* __restrict__ fcw, const float* __restrict__ fcb,
                             float* __restrict__ out) {
    int b = blockIdx.x;
    int tid = threadIdx.x;
    const int NF = DMODEL * (HEADS + 1);
    float a0 = 0.0f, a1 = 0.0f;

    for (int j = tid; j < NF; j += 256) {
        float x;
        if (j < HEADS * DMODEL) {
            int h = j / DMODEL, d = j % DMODEL;
            int n = b * HEADS + h;
            const float* cp = g_compose + (size_t)n * TT * DMODEL + d;
            float s = 0.0f;
            #pragma unroll
            for (int t = 0; t < TT; t++) s += cp[(size_t)t * DMODEL];
            x = s * (1.0f / (float)TT);
        } else {
            x = g_lrep[(size_t)b * DMODEL + (j - HEADS * DMODEL)];
        }
        a0 += x * fcw[j];
        a1 += x * fcw[NF + j];
    }

    __shared__ float s0[256], s1[256];
    s0[tid] = a0; s1[tid] = a1;
    __syncthreads();
    for (int off = 128; off > 0; off >>= 1) {
        if (tid < off) { s0[tid] += s0[tid + off]; s1[tid] += s1[tid + off]; }
        __syncthreads();
    }
    if (tid == 0) {
        float l0 = s0[0] + fcb[0], l1 = s1[0] + fcb[1];
        float m = fmaxf(l0, l1);
        float e0 = expf(l0 - m), e1 = expf(l1 - m);
        float inv = 1.0f / (e0 + e1);
        out[b * 2 + 0] = e0 * inv;
        out[b * 2 + 1] = e1 * inv;
    }
}

// ---------------- launch ----------------
extern "C" void kernel_launch(void* const* d_in, const int* in_sizes, int n_in,
                              void* d_out, int out_size) {
    const int*   sents = (const int*)d_in[0];
    const float* att   = (const float*)d_in[1];
    const float* logits= (const float*)d_in[2];
    const int*   mask  = (const int*)d_in[3];
    const float* wih_f = (const float*)d_in[4];
    const float* whh_f = (const float*)d_in[5];
    const float* bih_f = (const float*)d_in[6];
    const float* bhh_f = (const float*)d_in[7];
    const float* wih_r = (const float*)d_in[8];
    const float* whh_r = (const float*)d_in[9];
    const float* bih_r = (const float*)d_in[10];
    const float* bhh_r = (const float*)d_in[11];
    const float* fc_w  = (const float*)d_in[12];
    const float* fc_b  = (const float*)d_in[13];
    float* out = (float*)d_out;

    cudaFuncSetAttribute(gemm_hmma, cudaFuncAttributeMaxDynamicSharedMemorySize, GM_SMEM);

    masters_kernel<<<BH * 2, 256>>>(att, sents);
    build_slide<<<BH, 256>>>(logits, mask);

    {
        int nW = G4 * DIN;   // 1536*1536
        split_kernel<<<(nW + 255) / 256, 256>>>(wih_f, 0, 0, nW);
        split_kernel<<<(nW + 255) / 256, 256>>>(wih_r, 0, (size_t)nW, nW);
        int nH = G4 * HH;    // 1536*384
        split_kernel<<<(nH + 255) / 256, 256>>>(whh_f, 1, 0, nH);
        split_kernel<<<(nH + 255) / 256, 256>>>(whh_r, 1, (size_t)nH, nH);
        bias_combine<<<(2 * G4 + 255) / 256, 256>>>(bih_f, bhh_f, bih_r, bhh_r);
        zero_state<<<(2 * BH * G4 + 255) / 256, 256>>>();
    }

    // input GEMM: C(2304x3072) = slide @ [Wf;Wr]^T + bias
    gemm_hmma<<<dim3(2 * G4 / 128, BH * TT / 128, 1), 256, GM_SMEM>>>(0);

    for (int s = 0; s < TT; s++) {
        lstm_point<<<(2 * BH * HH + 255) / 256, 256>>>(s);
        if (s < TT - 1) {
            // gtmp[dir] = h[dir] @ whh[dir]^T for next step
            gemm_hmma<<<dim3(G4 / 128, BH / 128, 2), 256, GM_SMEM>>>(1);
        }
    }

    logits_rep_kernel<<<BATCH, 256>>>(logits, mask);
    final_kernel<<<BATCH, 256>>>(fc_w, fc_b, out);
}